// round 1
// baseline (speedup 1.0000x reference)
#include <cuda_runtime.h>
#include <cuda_bf16.h>
#include <math.h>

// ---------------------------------------------------------------------------
// Problem dims
// ---------------------------------------------------------------------------
#define BATCH 8
#define LSEQ  4096          // 64*64
#define DMODEL 256
#define NHEAD 8
#define DHEAD 32
#define MROWS (BATCH*LSEQ)  // 32768
#define NUM_LAYERS 4

// ---------------------------------------------------------------------------
// Scratch (device globals -- no allocations allowed)
// ---------------------------------------------------------------------------
__device__ float g_x  [MROWS * DMODEL];   // activations [b,l,d]
__device__ float g_q  [MROWS * DMODEL];   // Q, later reused as "merged"
__device__ float g_k  [MROWS * DMODEL];   // K, later reused as h2
__device__ float g_v  [MROWS * DMODEL];   // V
__device__ float g_msg[MROWS * DMODEL];   // attention output
__device__ float g_cat[MROWS * 2*DMODEL]; // [x | LN1(merged)]
__device__ float g_h1 [MROWS * 2*DMODEL]; // relu(cat @ W1)
__device__ float g_kv  [BATCH * NHEAD * DHEAD * DHEAD];
__device__ float g_ksum[BATCH * NHEAD * DHEAD];

// ---------------------------------------------------------------------------
// Positional encoding value for (channel c, position l)  (l = y*64 + x)
// ---------------------------------------------------------------------------
__device__ __forceinline__ float pe_val(int c, int l) {
    int i = c >> 2;
    int m = c & 3;
    float pos = (m < 2) ? (float)((l & 63) + 1) : (float)((l >> 6) + 1);
    // div = exp(-(2*i) * ln(10000)/128)
    float dv = expf(-(float)(2 * i) * 0.07195578490697396f);
    float a = pos * dv;
    return (m & 1) ? cosf(a) : sinf(a);
}

// ---------------------------------------------------------------------------
// K0: feats [b,c,l] -> x [b,l,c]  with positional encoding added
// grid (128, 8, 8)  block (32, 8)
// ---------------------------------------------------------------------------
__global__ void add_pe_transpose(const float* __restrict__ feats) {
    __shared__ float t[32][33];
    int b  = blockIdx.z;
    int c0 = blockIdx.y * 32;
    int l0 = blockIdx.x * 32;
    int tx = threadIdx.x, ty = threadIdx.y;
    #pragma unroll
    for (int i = ty; i < 32; i += 8) {
        int c = c0 + i, l = l0 + tx;
        t[i][tx] = feats[((size_t)b * DMODEL + c) * LSEQ + l] + pe_val(c, l);
    }
    __syncthreads();
    #pragma unroll
    for (int i = ty; i < 32; i += 8) {
        int l = l0 + i, c = c0 + tx;
        g_x[((size_t)b * LSEQ + l) * DMODEL + c] = t[tx][i];
    }
}

// ---------------------------------------------------------------------------
// K-last: x [b,l,c] -> out [b,c,l]
// ---------------------------------------------------------------------------
__global__ void transpose_out(float* __restrict__ out) {
    __shared__ float t[32][33];
    int b  = blockIdx.z;
    int c0 = blockIdx.y * 32;
    int l0 = blockIdx.x * 32;
    int tx = threadIdx.x, ty = threadIdx.y;
    #pragma unroll
    for (int i = ty; i < 32; i += 8)
        t[i][tx] = g_x[((size_t)b * LSEQ + l0 + i) * DMODEL + c0 + tx];
    __syncthreads();
    #pragma unroll
    for (int i = ty; i < 32; i += 8)
        out[((size_t)b * DMODEL + c0 + i) * LSEQ + l0 + tx] = t[tx][i];
}

// ---------------------------------------------------------------------------
// SGEMM: C[M,N] = A[M,K] @ B[K,N], row-major, all dims divisible.
// BM=BN=128, BK=8, 256 threads, 8x8 per thread.
// EPI: 0 = none, 1 = elu+1, 2 = relu
// ---------------------------------------------------------------------------
template <int EPI>
__device__ __forceinline__ float epi_fn(float v) {
    if (EPI == 1) return v > 0.f ? v + 1.f : expf(v);
    if (EPI == 2) return v > 0.f ? v : 0.f;
    return v;
}

template <int EPI>
__global__ __launch_bounds__(256) void sgemm(
    const float* __restrict__ A, const float* __restrict__ B,
    float* __restrict__ C, int M, int N, int K)
{
    __shared__ __align__(16) float As[8][128];
    __shared__ __align__(16) float Bs[8][128];

    int tid = threadIdx.x;
    int bn = blockIdx.x, bm = blockIdx.y;

    const float* Ablk = A + (size_t)bm * 128 * K;
    const float* Bblk = B + (size_t)bn * 128;

    int arow = tid >> 1,  acol = (tid & 1) * 4;   // 128x8 A tile
    int brow = tid >> 5,  bcol = (tid & 31) * 4;  // 8x128 B tile
    int ty = tid >> 4, tx = tid & 15;

    float acc[8][8];
    #pragma unroll
    for (int i = 0; i < 8; i++)
        #pragma unroll
        for (int j = 0; j < 8; j++) acc[i][j] = 0.f;

    for (int k0 = 0; k0 < K; k0 += 8) {
        float4 av = *(const float4*)(Ablk + (size_t)arow * K + k0 + acol);
        float4 bv = *(const float4*)(Bblk + (size_t)(k0 + brow) * N + bcol);
        As[acol + 0][arow] = av.x;
        As[acol + 1][arow] = av.y;
        As[acol + 2][arow] = av.z;
        As[acol + 3][arow] = av.w;
        *(float4*)(&Bs[brow][bcol]) = bv;
        __syncthreads();

        #pragma unroll
        for (int k = 0; k < 8; k++) {
            float4 a0 = *(const float4*)(&As[k][ty * 8]);
            float4 a1 = *(const float4*)(&As[k][ty * 8 + 4]);
            float4 b0 = *(const float4*)(&Bs[k][tx * 8]);
            float4 b1 = *(const float4*)(&Bs[k][tx * 8 + 4]);
            float ar[8] = {a0.x, a0.y, a0.z, a0.w, a1.x, a1.y, a1.z, a1.w};
            float br[8] = {b0.x, b0.y, b0.z, b0.w, b1.x, b1.y, b1.z, b1.w};
            #pragma unroll
            for (int i = 0; i < 8; i++)
                #pragma unroll
                for (int j = 0; j < 8; j++)
                    acc[i][j] += ar[i] * br[j];
        }
        __syncthreads();
    }

    float* Cp = C + (size_t)(bm * 128) * N + bn * 128;
    #pragma unroll
    for (int i = 0; i < 8; i++) {
        #pragma unroll
        for (int j = 0; j < 8; j += 4) {
            float4 o;
            o.x = epi_fn<EPI>(acc[i][j + 0]);
            o.y = epi_fn<EPI>(acc[i][j + 1]);
            o.z = epi_fn<EPI>(acc[i][j + 2]);
            o.w = epi_fn<EPI>(acc[i][j + 3]);
            *(float4*)(Cp + (size_t)(ty * 8 + i) * N + tx * 8 + j) = o;
        }
    }
}

// ---------------------------------------------------------------------------
// KV reduce: per (n,h): KV[d,v] = sum_l K[l,d]*V[l,v];  Ksum[d] = sum_l K[l,d]
// grid 64 blocks (n*8+h), 256 threads
// ---------------------------------------------------------------------------
__global__ __launch_bounds__(256) void kv_reduce() {
    int n = blockIdx.x >> 3;
    int h = blockIdx.x & 7;
    const float* Kp = g_k + (size_t)n * LSEQ * DMODEL + h * DHEAD;
    const float* Vp = g_v + (size_t)n * LSEQ * DMODEL + h * DHEAD;

    __shared__ float sK[8][32];
    __shared__ float sV[8][32];

    int tid = threadIdx.x;
    int d0 = tid >> 3;            // 0..31
    int v0 = (tid & 7) * 4;       // 0,4,...,28
    float acc0 = 0.f, acc1 = 0.f, acc2 = 0.f, acc3 = 0.f;
    float ks = 0.f;
    int lr = tid >> 5, lc = tid & 31;

    for (int l0 = 0; l0 < LSEQ; l0 += 8) {
        sK[lr][lc] = Kp[(size_t)(l0 + lr) * DMODEL + lc];
        sV[lr][lc] = Vp[(size_t)(l0 + lr) * DMODEL + lc];
        __syncthreads();
        #pragma unroll
        for (int r = 0; r < 8; r++) {
            float kd = sK[r][d0];
            acc0 += kd * sV[r][v0 + 0];
            acc1 += kd * sV[r][v0 + 1];
            acc2 += kd * sV[r][v0 + 2];
            acc3 += kd * sV[r][v0 + 3];
            if ((tid & 7) == 0) ks += kd;
        }
        __syncthreads();
    }

    float* kvp = g_kv + (size_t)blockIdx.x * DHEAD * DHEAD + d0 * DHEAD + v0;
    kvp[0] = acc0; kvp[1] = acc1; kvp[2] = acc2; kvp[3] = acc3;
    if ((tid & 7) == 0) g_ksum[(size_t)blockIdx.x * DHEAD + d0] = ks;
}

// ---------------------------------------------------------------------------
// Attention apply: msg[l,h,v] = (sum_d Q[l,h,d]*KV[h,d,v]) / (Q.Ksum + eps)
// grid (32 l-tiles, 8 batch), 256 threads; 128 rows per block.
// ---------------------------------------------------------------------------
__global__ __launch_bounds__(256) void attn_apply() {
    int n  = blockIdx.y;
    int l0 = blockIdx.x * 128;
    __shared__ float sKV[NHEAD][DHEAD][DHEAD];   // 32 KB
    __shared__ float sKs[NHEAD][DHEAD];

    int tid = threadIdx.x;
    const float* kvp = g_kv + (size_t)n * NHEAD * DHEAD * DHEAD;
    for (int i = tid; i < NHEAD * DHEAD * DHEAD; i += 256)
        ((float*)sKV)[i] = kvp[i];
    for (int i = tid; i < NHEAD * DHEAD; i += 256)
        ((float*)sKs)[i] = g_ksum[(size_t)n * NHEAD * DHEAD + i];
    __syncthreads();

    #pragma unroll
    for (int p = 0; p < 4; p++) {
        int i  = p * 256 + tid;    // 0..1023
        int h  = i >> 7;           // warp-uniform
        int ll = i & 127;
        const float* qp = g_q + ((size_t)n * LSEQ + l0 + ll) * DMODEL + h * DHEAD;
        float q[32];
        #pragma unroll
        for (int d = 0; d < 32; d += 4) {
            float4 t = *(const float4*)(qp + d);
            q[d] = t.x; q[d + 1] = t.y; q[d + 2] = t.z; q[d + 3] = t.w;
        }
        float zdot = 0.f;
        #pragma unroll
        for (int d = 0; d < 32; d++) zdot += q[d] * sKs[h][d];
        float z = 1.f / (zdot + 1e-6f);

        float* mp = g_msg + ((size_t)n * LSEQ + l0 + ll) * DMODEL + h * DHEAD;
        #pragma unroll
        for (int v = 0; v < 32; v += 4) {
            float a0 = 0.f, a1 = 0.f, a2 = 0.f, a3 = 0.f;
            #pragma unroll
            for (int d = 0; d < 32; d++) {
                float qq = q[d];
                a0 += qq * sKV[h][d][v + 0];
                a1 += qq * sKV[h][d][v + 1];
                a2 += qq * sKV[h][d][v + 2];
                a3 += qq * sKV[h][d][v + 3];
            }
            float4 o = {a0 * z, a1 * z, a2 * z, a3 * z};
            *(float4*)(mp + v) = o;
        }
    }
}

// ---------------------------------------------------------------------------
// LayerNorm helpers: one warp per 256-wide row, 8 rows per block
// ---------------------------------------------------------------------------
__device__ __forceinline__ float warp_sum(float v) {
    #pragma unroll
    for (int o = 16; o > 0; o >>= 1) v += __shfl_xor_sync(0xffffffffu, v, o);
    return v;
}

// LN1: cat[:,0:256] = x, cat[:,256:512] = LN(merged)
__global__ __launch_bounds__(256) void ln1_cat(
    const float* __restrict__ inp, const float* __restrict__ gam,
    const float* __restrict__ bet)
{
    int row  = blockIdx.x * 8 + (threadIdx.x >> 5);
    int lane = threadIdx.x & 31;
    const float* ip = inp + (size_t)row * DMODEL;
    float v[8]; float s = 0.f;
    #pragma unroll
    for (int j = 0; j < 8; j++) { v[j] = ip[lane + 32 * j]; s += v[j]; }
    s = warp_sum(s);
    float mu = s * (1.f / 256.f);
    float s2 = 0.f;
    #pragma unroll
    for (int j = 0; j < 8; j++) { float d = v[j] - mu; s2 += d * d; }
    s2 = warp_sum(s2);
    float rs = rsqrtf(s2 * (1.f / 256.f) + 1e-5f);

    float* cp = g_cat + (size_t)row * 2 * DMODEL;
    const float* xp = g_x + (size_t)row * DMODEL;
    #pragma unroll
    for (int j = 0; j < 8; j++) {
        int c = lane + 32 * j;
        cp[c] = xp[c];
        cp[DMODEL + c] = (v[j] - mu) * rs * gam[c] + bet[c];
    }
}

// LN2 + residual: x += LN(h2)
__global__ __launch_bounds__(256) void ln2_res(
    const float* __restrict__ inp, const float* __restrict__ gam,
    const float* __restrict__ bet)
{
    int row  = blockIdx.x * 8 + (threadIdx.x >> 5);
    int lane = threadIdx.x & 31;
    const float* ip = inp + (size_t)row * DMODEL;
    float v[8]; float s = 0.f;
    #pragma unroll
    for (int j = 0; j < 8; j++) { v[j] = ip[lane + 32 * j]; s += v[j]; }
    s = warp_sum(s);
    float mu = s * (1.f / 256.f);
    float s2 = 0.f;
    #pragma unroll
    for (int j = 0; j < 8; j++) { float d = v[j] - mu; s2 += d * d; }
    s2 = warp_sum(s2);
    float rs = rsqrtf(s2 * (1.f / 256.f) + 1e-5f);

    float* xp = g_x + (size_t)row * DMODEL;
    #pragma unroll
    for (int j = 0; j < 8; j++) {
        int c = lane + 32 * j;
        xp[c] += (v[j] - mu) * rs * gam[c] + bet[c];
    }
}

// ---------------------------------------------------------------------------
// Host orchestration
// ---------------------------------------------------------------------------
extern "C" void kernel_launch(void* const* d_in, const int* in_sizes, int n_in,
                              void* d_out, int out_size)
{
    const float* feats  = (const float*)d_in[0];
    const float* Wq     = (const float*)d_in[1];
    const float* Wk     = (const float*)d_in[2];
    const float* Wv     = (const float*)d_in[3];
    const float* Wm     = (const float*)d_in[4];
    const float* W1     = (const float*)d_in[5];
    const float* W2     = (const float*)d_in[6];
    const float* ln1g   = (const float*)d_in[7];
    const float* ln1b   = (const float*)d_in[8];
    const float* ln2g   = (const float*)d_in[9];
    const float* ln2b   = (const float*)d_in[10];

    float *px, *pq, *pk, *pv, *pmsg, *pcat, *ph1;
    cudaGetSymbolAddress((void**)&px,   g_x);
    cudaGetSymbolAddress((void**)&pq,   g_q);
    cudaGetSymbolAddress((void**)&pk,   g_k);
    cudaGetSymbolAddress((void**)&pv,   g_v);
    cudaGetSymbolAddress((void**)&pmsg, g_msg);
    cudaGetSymbolAddress((void**)&pcat, g_cat);
    cudaGetSymbolAddress((void**)&ph1,  g_h1);

    dim3 tb(32, 8);
    add_pe_transpose<<<dim3(LSEQ / 32, DMODEL / 32, BATCH), tb>>>(feats);

    const int M = MROWS;
    dim3 blk(256);
    dim3 grid_d (DMODEL / 128, M / 128);       // N=256
    dim3 grid_2d(2 * DMODEL / 128, M / 128);   // N=512

    for (int i = 0; i < NUM_LAYERS; i++) {
        const float* wq = Wq + (size_t)i * DMODEL * DMODEL;
        const float* wk = Wk + (size_t)i * DMODEL * DMODEL;
        const float* wv = Wv + (size_t)i * DMODEL * DMODEL;
        const float* wm = Wm + (size_t)i * DMODEL * DMODEL;
        const float* w1 = W1 + (size_t)i * 2 * DMODEL * 2 * DMODEL;
        const float* w2 = W2 + (size_t)i * 2 * DMODEL * DMODEL;

        // Q = elu(x@Wq)+1, K = elu(x@Wk)+1, V = x@Wv (unscaled; /L and *L cancel)
        sgemm<1><<<grid_d, blk>>>(px, wq, pq, M, DMODEL, DMODEL);
        sgemm<1><<<grid_d, blk>>>(px, wk, pk, M, DMODEL, DMODEL);
        sgemm<0><<<grid_d, blk>>>(px, wv, pv, M, DMODEL, DMODEL);

        kv_reduce<<<BATCH * NHEAD, 256>>>();
        attn_apply<<<dim3(LSEQ / 128, BATCH), 256>>>();

        // merged = msg @ Wm  (reuse g_q)
        sgemm<0><<<grid_d, blk>>>(pmsg, wm, pq, M, DMODEL, DMODEL);

        // cat = [x | LN1(merged)]
        ln1_cat<<<M / 8, 256>>>(pq, ln1g + i * DMODEL, ln1b + i * DMODEL);

        // h1 = relu(cat @ W1);  h2 = h1 @ W2 (reuse g_k)
        sgemm<2><<<grid_2d, blk>>>(pcat, w1, ph1, M, 2 * DMODEL, 2 * DMODEL);
        sgemm<0><<<grid_d, blk>>>(ph1, w2, pk, M, DMODEL, 2 * DMODEL);

        // x += LN2(h2)
        ln2_res<<<M / 8, 256>>>(pk, ln2g + i * DMODEL, ln2b + i * DMODEL);
    }

    transpose_out<<<dim3(LSEQ / 32, DMODEL / 32, BATCH), tb>>>((float*)d_out);
}